// round 8
// baseline (speedup 1.0000x reference)
#include <cuda_runtime.h>
#include <math.h>

#define T_ 256
#define B_ 256
#define C_ 64
#define H_ 512
#define G_ 2048
#define K_ 640   // 512 (h) + 64 (c_c) + 64 (m)
#define NBLK 128

// ---- static device scratch ----
__device__ float g_v[T_*B_*C_];
__device__ float g_m[T_*B_*C_];
__device__ float g_d[T_*B_*C_];
__device__ float g_gh[T_*B_*H_];    // gamma_h (134MB)
__device__ float g_al[T_*B_*C_];
__device__ float g_A[B_*K_];        // [h_dec | c_c | m]
__device__ float g_h[B_*H_];
__device__ float g_Wcat[G_*K_];     // [u*4+gate][k]
__device__ float g_bias[G_];
__device__ float g_WfR[C_*C_];      // W_feat row-major, zero diagonal
__device__ float g_WcT[2*C_*C_];
__device__ float g_diag[C_];
__device__ unsigned g_bar[4][64];   // [grp][0]=arrive, [grp][32]=gen (separate L2 lines)

// ---- f32x2 packed FMA helpers ----
__device__ __forceinline__ unsigned long long dup2(float a) {
    unsigned long long r;
    asm("mov.b64 %0, {%1,%1};" : "=l"(r) : "f"(a));
    return r;
}
__device__ __forceinline__ unsigned long long pk2(float lo, float hi) {
    unsigned long long r;
    asm("mov.b64 %0, {%1,%2};" : "=l"(r) : "f"(lo), "f"(hi));
    return r;
}
__device__ __forceinline__ void ffma2(unsigned long long& d, unsigned long long a,
                                      unsigned long long b) {
    asm("fma.rn.f32x2 %0, %1, %2, %0;" : "+l"(d) : "l"(a), "l"(b));
}
__device__ __forceinline__ float2 upk2(unsigned long long v) {
    float2 f;
    asm("mov.b64 {%0,%1}, %2;" : "=f"(f.x), "=f"(f.y) : "l"(v));
    return f;
}

// ---- group-local grid barrier: 32 blocks, acq/rel, no L1 flush ----
__device__ __forceinline__ void gbar(int grp) {
    __syncthreads();
    if (threadIdx.x == 0) {
        unsigned* arr = &g_bar[grp][0];
        unsigned* gen = &g_bar[grp][32];
        unsigned g0;
        asm volatile("ld.acquire.gpu.global.u32 %0, [%1];" : "=r"(g0) : "l"(gen));
        unsigned old;
        asm volatile("atom.acq_rel.gpu.global.add.u32 %0, [%1], 1;"
                     : "=r"(old) : "l"(arr));
        if (old == 31u) {
            asm volatile("st.relaxed.gpu.global.u32 [%0], 0;" :: "l"(arr));
            asm volatile("red.release.gpu.global.add.u32 [%0], 1;" :: "l"(gen));
        } else {
            unsigned g;
            do {
                __nanosleep(32);
                asm volatile("ld.acquire.gpu.global.u32 %0, [%1];" : "=r"(g) : "l"(gen));
            } while (g == g0);
        }
    }
    __syncthreads();
}

// ======================= preamble kernels =======================

__global__ void k_pack_w(const float* __restrict__ Wih, const float* __restrict__ Whh) {
    for (int i = blockIdx.x*blockDim.x + threadIdx.x; i < G_*K_; i += gridDim.x*blockDim.x) {
        int gp = i / K_, k = i % K_;
        int u = gp >> 2, gate = gp & 3;
        int go = gate*H_ + u;
        float w;
        if (k < H_)            w = Whh[go*H_ + k];
        else if (k < H_ + C_)  w = Wih[go*2*C_ + (k - H_)];
        else                   w = Wih[go*2*C_ + C_ + (k - H_ - C_)];
        g_Wcat[i] = w;
    }
}

__global__ void k_pack_misc(const float* __restrict__ Wfeat, const float* __restrict__ Wcomb,
                            const float* __restrict__ bih,   const float* __restrict__ bhh,
                            const float* __restrict__ Wgx) {
    int tid = blockIdx.x*blockDim.x + threadIdx.x, n = gridDim.x*blockDim.x;
    for (int i = tid; i < C_*C_; i += n) { int r=i/C_, j=i%C_; g_WfR[i] = (r==j)?0.f:Wfeat[i]; }
    for (int i = tid; i < 2*C_*C_; i += n) { int j=i/C_, c=i%C_; g_WcT[i] = Wcomb[c*2*C_ + j]; }
    for (int i = tid; i < C_; i += n) g_diag[i] = Wgx[i*C_ + i];
    for (int i = tid; i < G_; i += n) { int u=i>>2, g=i&3; int go=g*H_+u; g_bias[i] = bih[go] + bhh[go]; }
    for (int i = tid; i < B_*H_; i += n) g_h[i] = 0.f;
}

__global__ void k_prep(const float* __restrict__ data) {
    int id = blockIdx.x*blockDim.x + threadIdx.x;
    if (id >= B_*C_) return;
    int b = id / C_, c = id % C_;
    float dec = 1.f, m_prev = 1.f;
    for (int t = 0; t < T_; t++) {
        float x = data[(b*T_ + t)*C_ + c];
        float m = (x != x) ? 0.f : 1.f;
        float v = (x != x) ? 0.f : x;
        float del;
        if (t == 0) del = 0.f;
        else if (t == 1) del = 1.f;
        else { dec = (m_prev == 1.f) ? 1.f : dec + 1.f; del = dec; }
        int o = (t*B_ + b)*C_ + c;
        g_v[o] = v; g_m[o] = m; g_d[o] = del;
        m_prev = m;
    }
}

__global__ void __launch_bounds__(256) k_gammaH(const float* __restrict__ Wgh,
                                                const float* __restrict__ bgh) {
    __shared__ __align__(16) float As[2][32][68];
    __shared__ __align__(16) float Ws[2][32][68];
    int m0 = (blockIdx.x >> 3) << 6;
    int n0 = (blockIdx.x & 7) << 6;
    int tid = threadIdx.x, tx = tid & 15, ty = tid >> 4;
    int mm = tid >> 3, kk4 = (tid & 7) << 2;

    unsigned long long acc[4][2] = {};
    #define STAGE_G(buf, kc) { \
        float4 a0 = *(const float4*)&g_d[(m0+mm)*C_ + (kc) + kk4]; \
        float4 a1 = *(const float4*)&g_d[(m0+mm+32)*C_ + (kc) + kk4]; \
        float4 w0 = *(const float4*)&Wgh[(n0+mm)*C_ + (kc) + kk4]; \
        float4 w1 = *(const float4*)&Wgh[(n0+mm+32)*C_ + (kc) + kk4]; \
        As[buf][kk4+0][mm]=a0.x; As[buf][kk4+1][mm]=a0.y; As[buf][kk4+2][mm]=a0.z; As[buf][kk4+3][mm]=a0.w; \
        As[buf][kk4+0][mm+32]=a1.x; As[buf][kk4+1][mm+32]=a1.y; As[buf][kk4+2][mm+32]=a1.z; As[buf][kk4+3][mm+32]=a1.w; \
        Ws[buf][kk4+0][mm]=w0.x; Ws[buf][kk4+1][mm]=w0.y; Ws[buf][kk4+2][mm]=w0.z; Ws[buf][kk4+3][mm]=w0.w; \
        Ws[buf][kk4+0][mm+32]=w1.x; Ws[buf][kk4+1][mm+32]=w1.y; Ws[buf][kk4+2][mm+32]=w1.z; Ws[buf][kk4+3][mm+32]=w1.w; }

    STAGE_G(0, 0);
    __syncthreads();
    #pragma unroll
    for (int ch = 0; ch < 2; ch++) {
        int buf = ch & 1;
        if (ch < 1) STAGE_G(1, 32);
        #pragma unroll
        for (int kk = 0; kk < 32; kk++) {
            float4 a = *(const float4*)&As[buf][kk][tx*4];
            ulonglong2 w = *(const ulonglong2*)&Ws[buf][kk][ty*4];
            unsigned long long a0 = dup2(a.x), a1 = dup2(a.y), a2 = dup2(a.z), a3 = dup2(a.w);
            ffma2(acc[0][0], a0, w.x); ffma2(acc[0][1], a0, w.y);
            ffma2(acc[1][0], a1, w.x); ffma2(acc[1][1], a1, w.y);
            ffma2(acc[2][0], a2, w.x); ffma2(acc[2][1], a2, w.y);
            ffma2(acc[3][0], a3, w.x); ffma2(acc[3][1], a3, w.y);
        }
        __syncthreads();
    }
    int u0 = n0 + ty*4;
    float4 b4 = *(const float4*)&bgh[u0];
    #pragma unroll
    for (int mi = 0; mi < 4; mi++) {
        int row = m0 + tx*4 + mi;
        float2 p0 = upk2(acc[mi][0]), p1 = upk2(acc[mi][1]);
        float4 v;
        v.x = expf(-fmaxf(p0.x + b4.x, 0.f));
        v.y = expf(-fmaxf(p0.y + b4.y, 0.f));
        v.z = expf(-fmaxf(p1.x + b4.z, 0.f));
        v.w = expf(-fmaxf(p1.y + b4.w, 0.f));
        *(float4*)&g_gh[row*H_ + u0] = v;
    }
    #undef STAGE_G
}

__global__ void k_alpha(const float* __restrict__ bgx, const float* __restrict__ bcomb) {
    __shared__ float gx[4][C_], ms[4][C_];
    int row0 = blockIdx.x * 8;
    int r = threadIdx.x >> 6, i = threadIdx.x & 63;
    for (int p = 0; p < 2; p++) {
        int row = row0 + p*4 + r;
        float d = g_d[row*C_ + i], m = g_m[row*C_ + i];
        gx[r][i] = expf(-fmaxf(d*g_diag[i] + bgx[i], 0.f));
        ms[r][i] = m;
        __syncthreads();
        float acc = bcomb[i];
        #pragma unroll 8
        for (int j = 0; j < C_; j++) acc += gx[r][j] * g_WcT[j*C_ + i];
        #pragma unroll 8
        for (int j = 0; j < C_; j++) acc += ms[r][j] * g_WcT[(C_ + j)*C_ + i];
        g_al[row*C_ + i] = acc;
        __syncthreads();
    }
}

// ======================= persistent sequential kernel =======================
#define SW_OFF   0
#define SW_SZ    (K_*68)
#define AS_OFF   (SW_OFF + SW_SZ)
#define AS_SZ    (2*32*68)
#define HD_OFF   (AS_OFF + AS_SZ)
#define PART_OFF (HD_OFF + 2*H_)
#define XH_OFF   (PART_OFF + 256)
#define XC_OFF   (XH_OFF + 2*C_)
#define MS_OFF   (XC_OFF + 2*C_)
#define VS_OFF   (MS_OFF + 2*C_)
#define SMEM_FLOATS (VS_OFF + 2*C_)

__global__ void __launch_bounds__(256, 1) k_seq(const float* __restrict__ Whist,
                                                const float* __restrict__ bhist,
                                                const float* __restrict__ bfeat,
                                                float* __restrict__ out) {
    extern __shared__ __align__(16) float sm[];
    float* Wsm  = sm + SW_OFF;
    float* As   = sm + AS_OFF;
    float* hd   = sm + HD_OFF;
    float* part = sm + PART_OFF;
    float* xh   = sm + XH_OFF;
    float* xc   = sm + XC_OFF;
    float* msh  = sm + MS_OFF;
    float* vsh  = sm + VS_OFF;

    int tid = threadIdx.x, blk = blockIdx.x;
    int grp = blk & 3, nt = blk >> 2;
    int m0 = grp << 6, n0 = nt << 6;
    int tx = tid & 15, ty = tid >> 4;
    int mm = tid >> 3, kk4 = (tid & 7) << 2;
    int b0 = m0 + nt*2;                         // phase-A rows within own group

    // prologue: W slice to smem (once), bias+cell state in regs
    for (int i = tid; i < 64*K_; i += 256) {
        int nl = i / K_, k = i - nl*K_;
        Wsm[k*68 + nl] = g_Wcat[(n0 + nl)*K_ + k];
    }
    float4 bq = *(const float4*)&g_bias[n0 + ty*4];
    int u_ep = (n0 + ty*4) >> 2;
    float cst[4] = {0.f, 0.f, 0.f, 0.f};
    __syncthreads();

    for (int t = 0; t < T_; t++) {
        // ---------------- phase A ----------------
        if (tid < 128) {
            int r = tid >> 6, c = tid & 63;
            int o = (t*B_ + b0 + r)*C_ + c;
            msh[tid] = g_m[o]; vsh[tid] = g_v[o];
        }
        {
            int r = tid >> 7, u0 = (tid & 127) * 4;
            int b = b0 + r;
            float4 h4 = __ldcg((const float4*)&g_h[b*H_ + u0]);
            float4 gh4 = *(const float4*)&g_gh[(t*B_ + b)*H_ + u0];
            float4 v = make_float4(h4.x*gh4.x, h4.y*gh4.y, h4.z*gh4.z, h4.w*gh4.w);
            *(float4*)&hd[r*H_ + u0] = v;
            __stcg((float4*)&g_A[b*K_ + u0], v);
        }
        __syncthreads();
        {   // x_h GEMV: thread (half, r, c); W row-contiguous, natural-pair FFMA2
            int half = tid >> 7, r = (tid >> 6) & 1, c = tid & 63;
            const float4* wp = (const float4*)&Whist[c*H_ + half*256];
            const float4* hp = (const float4*)&hd[r*H_ + half*256];
            unsigned long long a0 = 0ull, a1 = 0ull;
            #pragma unroll 16
            for (int i = 0; i < 64; i++) {
                float4 w = wp[i];
                float4 h = hp[i];
                ffma2(a0, pk2(h.x, h.y), pk2(w.x, w.y));
                ffma2(a1, pk2(h.z, h.w), pk2(w.z, w.w));
            }
            float2 p0 = upk2(a0), p1 = upk2(a1);
            part[half*128 + r*64 + c] = (p0.x + p0.y) + (p1.x + p1.y);
        }
        __syncthreads();
        if (tid < 128) {
            int c = tid & 63;
            float x_h = part[tid] + part[tid + 128] + bhist[c];
            xh[tid] = x_h;
            float m = msh[tid], v = vsh[tid];
            xc[tid] = m*v + (1.f - m)*x_h;
        }
        __syncthreads();
        if (tid < 128) {
            int r = tid >> 6, i = tid & 63;
            int b = b0 + r;
            const float4* fp = (const float4*)&g_WfR[i*C_];
            const float4* xp = (const float4*)&xc[r*C_];
            unsigned long long z0 = 0ull, z1 = 0ull;
            #pragma unroll
            for (int j = 0; j < 16; j++) {
                float4 w = fp[j];
                float4 x = xp[j];
                ffma2(z0, pk2(x.x, x.y), pk2(w.x, w.y));
                ffma2(z1, pk2(x.z, x.w), pk2(w.z, w.w));
            }
            float2 q0 = upk2(z0), q1 = upk2(z1);
            float z = (q0.x + q0.y) + (q1.x + q1.y) + bfeat[i];
            float al = g_al[(t*B_ + b)*C_ + i];
            float x_h = xh[tid];
            float ch = al*z + (1.f - al)*x_h;
            float m = msh[tid], v = vsh[tid];
            float cc = m*v + (1.f - m)*ch;
            out[(b*T_ + t)*C_ + i] = cc;
            __stcg(&g_A[b*K_ + H_ + i], cc);
            __stcg(&g_A[b*K_ + H_ + C_ + i], m);
        }
        gbar(grp);   // group's g_A complete

        // ---------------- phase B ----------------
        unsigned long long acc[4][2] = {};
        #define STAGE_A(buf, kc) { \
            float4 a0 = __ldcg((const float4*)&g_A[(m0+mm)*K_ + (kc) + kk4]); \
            float4 a1 = __ldcg((const float4*)&g_A[(m0+mm+32)*K_ + (kc) + kk4]); \
            float* Ab = As + (buf)*(32*68); \
            Ab[(kk4+0)*68+mm]=a0.x; Ab[(kk4+1)*68+mm]=a0.y; Ab[(kk4+2)*68+mm]=a0.z; Ab[(kk4+3)*68+mm]=a0.w; \
            Ab[(kk4+0)*68+mm+32]=a1.x; Ab[(kk4+1)*68+mm+32]=a1.y; Ab[(kk4+2)*68+mm+32]=a1.z; Ab[(kk4+3)*68+mm+32]=a1.w; }

        STAGE_A(0, 0);
        __syncthreads();
        for (int ch = 0; ch < 20; ch++) {
            int buf = ch & 1;
            if (ch < 19) STAGE_A(buf ^ 1, (ch + 1) * 32);
            const float* Ab = As + buf*(32*68);
            const float* Wb = Wsm + (ch*32)*68;
            #pragma unroll
            for (int kk = 0; kk < 32; kk++) {
                float4 a = *(const float4*)&Ab[kk*68 + tx*4];
                ulonglong2 w = *(const ulonglong2*)&Wb[kk*68 + ty*4];
                unsigned long long a0 = dup2(a.x), a1 = dup2(a.y), a2 = dup2(a.z), a3 = dup2(a.w);
                ffma2(acc[0][0], a0, w.x); ffma2(acc[0][1], a0, w.y);
                ffma2(acc[1][0], a1, w.x); ffma2(acc[1][1], a1, w.y);
                ffma2(acc[2][0], a2, w.x); ffma2(acc[2][1], a2, w.y);
                ffma2(acc[3][0], a3, w.x); ffma2(acc[3][1], a3, w.y);
            }
            __syncthreads();
        }
        #undef STAGE_A

        // LSTM epilogue
        #pragma unroll
        for (int mi = 0; mi < 4; mi++) {
            int b = m0 + tx*4 + mi;
            float2 p0 = upk2(acc[mi][0]), p1 = upk2(acc[mi][1]);
            float gi = p0.x + bq.x;
            float gf = p0.y + bq.y;
            float gg = p1.x + bq.z;
            float go = p1.y + bq.w;
            float co = cst[mi];
            float si = 1.f/(1.f + expf(-gi));
            float sf = 1.f/(1.f + expf(-gf));
            float so = 1.f/(1.f + expf(-go));
            float cn = sf*co + si*tanhf(gg);
            cst[mi] = cn;
            __stcg(&g_h[b*H_ + u_ep], so*tanhf(cn));
        }
        gbar(grp);   // group's g_h complete
    }
}

extern "C" void kernel_launch(void* const* d_in, const int* in_sizes, int n_in,
                              void* d_out, int out_size) {
    const float* data  = (const float*)d_in[0];
    const float* Wih   = (const float*)d_in[1];
    const float* Whh   = (const float*)d_in[2];
    const float* bih   = (const float*)d_in[3];
    const float* bhh   = (const float*)d_in[4];
    const float* Wgh   = (const float*)d_in[5];
    const float* bgh   = (const float*)d_in[6];
    const float* Wgx   = (const float*)d_in[7];
    const float* bgx   = (const float*)d_in[8];
    const float* Whist = (const float*)d_in[9];
    const float* bhist = (const float*)d_in[10];
    const float* Wfeat = (const float*)d_in[11];
    const float* bfeat = (const float*)d_in[12];
    const float* Wcomb = (const float*)d_in[13];
    const float* bcomb = (const float*)d_in[14];
    float* out = (float*)d_out;

    static int smem_set = 0;
    if (!smem_set) {
        cudaFuncSetAttribute(k_seq, cudaFuncAttributeMaxDynamicSharedMemorySize,
                             SMEM_FLOATS * sizeof(float));
        smem_set = 1;
    }

    k_pack_w<<<2048, 256>>>(Wih, Whh);
    k_pack_misc<<<256, 256>>>(Wfeat, Wcomb, bih, bhh, Wgx);
    k_prep<<<64, 256>>>(data);
    k_gammaH<<<8192, 256>>>(Wgh, bgh);
    k_alpha<<<8192, 256>>>(bgx, bcomb);
    k_seq<<<NBLK, 256, SMEM_FLOATS * sizeof(float)>>>(Whist, bhist, bfeat, out);
}